// round 5
// baseline (speedup 1.0000x reference)
#include <cuda_runtime.h>
#include <cstdint>

#define Bn 16
#define Tn 256
#define Cn 6
#define En 512
#define Hn 8
#define HD 64
#define NTOK (Bn*Tn*Cn)      // 24576
#define NHEADS (Bn*Hn*Cn)    // 768

// ---- device-global scratch (no allocations allowed) ----
__device__ float g_q[(size_t)NHEADS * Tn * HD];
__device__ float g_k[(size_t)NHEADS * Tn * HD];
__device__ float g_v[(size_t)NHEADS * Tn * HD];
__device__ float g_y[(size_t)NTOK * En];       // attention output, tf32-rounded
__device__ float g_xr[(size_t)NTOK * En];      // x rounded to tf32
__device__ float g_wr[(size_t)4 * En * En];    // Wq,Wk,Wv,Wp rounded to tf32

// ---------------------------------------------------------------------------
__device__ __forceinline__ float tf32r(float x) {
    uint32_t u;
    asm("cvt.rna.tf32.f32 %0, %1;" : "=r"(u) : "f"(x));
    return __uint_as_float(u);
}

__device__ __forceinline__ void cpasync16(float* smem_dst, const float* gsrc) {
    uint32_t s = (uint32_t)__cvta_generic_to_shared(smem_dst);
    asm volatile("cp.async.ca.shared.global [%0], [%1], 16;\n" :: "r"(s), "l"(gsrc));
}

__device__ __forceinline__ void mma_tf32(float c[4], const uint32_t a[4], const uint32_t b[2]) {
    asm volatile(
        "mma.sync.aligned.m16n8k8.row.col.f32.tf32.tf32.f32 "
        "{%0,%1,%2,%3}, {%4,%5,%6,%7}, {%8,%9}, {%0,%1,%2,%3};"
        : "+f"(c[0]), "+f"(c[1]), "+f"(c[2]), "+f"(c[3])
        : "r"(a[0]), "r"(a[1]), "r"(a[2]), "r"(a[3]), "r"(b[0]), "r"(b[1]));
}

// ---------------------------------------------------------------------------
// Prepass: round inputs to tf32 once.
// ---------------------------------------------------------------------------
__global__ void round_x_kernel(const float* __restrict__ x) {
    int i = blockIdx.x * 256 + threadIdx.x;
    float4 v = ((const float4*)x)[i];
    float4 o;
    o.x = tf32r(v.x); o.y = tf32r(v.y); o.z = tf32r(v.z); o.w = tf32r(v.w);
    ((float4*)g_xr)[i] = o;
}

__global__ void round_w_kernel(const float* __restrict__ Wq, const float* __restrict__ Wk,
                               const float* __restrict__ Wv, const float* __restrict__ Wp) {
    int i = blockIdx.x * 256 + threadIdx.x;
    int w = i >> 16;
    int off = i & 65535;
    const float* src = (w == 0) ? Wq : (w == 1) ? Wk : (w == 2) ? Wv : Wp;
    float4 v = ((const float4*)src)[off];
    float4 o;
    o.x = tf32r(v.x); o.y = tf32r(v.y); o.z = tf32r(v.z); o.w = tf32r(v.w);
    ((float4*)g_wr)[i] = o;
}

// ---------------------------------------------------------------------------
// tf32 MMA GEMM core
// ---------------------------------------------------------------------------
#define SSTR 20
#define BK   16

__device__ __forceinline__ void load_tile(float* As, float* Bs,
                                          const float* gA, const float* gB, int k0) {
    const int tid = threadIdx.x;
    #pragma unroll
    for (int it = 0; it < 2; it++) {
        int chunk = it * 256 + tid;
        int m  = chunk >> 2;
        int kc = (chunk & 3) * 4;
        cpasync16(As + m * SSTR + kc, gA + (size_t)m * En + k0 + kc);
        cpasync16(Bs + m * SSTR + kc, gB + (size_t)m * En + k0 + kc);
    }
    asm volatile("cp.async.commit_group;\n" ::);
}

__device__ __forceinline__ void compute_tile(const float* As, const float* Bs,
                                             float acc[4][4][4],
                                             int wm, int wn, int gr, int ctl) {
    #pragma unroll
    for (int ks = 0; ks < BK; ks += 8) {
        uint32_t a[4][4], b[4][2];
        #pragma unroll
        for (int mi = 0; mi < 4; mi++) {
            const float* p = As + (wm * 64 + mi * 16 + gr) * SSTR + ks + ctl;
            a[mi][0] = __float_as_uint(p[0]);
            a[mi][1] = __float_as_uint(p[8 * SSTR]);
            a[mi][2] = __float_as_uint(p[4]);
            a[mi][3] = __float_as_uint(p[8 * SSTR + 4]);
        }
        #pragma unroll
        for (int ni = 0; ni < 4; ni++) {
            const float* p = Bs + (wn * 32 + ni * 8 + gr) * SSTR + ks + ctl;
            b[ni][0] = __float_as_uint(p[0]);
            b[ni][1] = __float_as_uint(p[4]);
        }
        #pragma unroll
        for (int mi = 0; mi < 4; mi++)
            #pragma unroll
            for (int ni = 0; ni < 4; ni++)
                mma_tf32(acc[mi][ni], a[mi], b[ni]);
    }
}

#define GEMM_MAINLOOP(gA, gB)                                          \
    load_tile(As[0], Bs[0], gA, gB, 0);                                \
    _Pragma("unroll 1")                                                \
    for (int kt = 0; kt < En / BK; kt++) {                             \
        if (kt + 1 < En / BK) {                                        \
            load_tile(As[(kt + 1) & 1], Bs[(kt + 1) & 1], gA, gB,      \
                      (kt + 1) * BK);                                  \
            asm volatile("cp.async.wait_group 1;\n" ::);               \
        } else {                                                       \
            asm volatile("cp.async.wait_group 0;\n" ::);               \
        }                                                              \
        __syncthreads();                                               \
        compute_tile(As[kt & 1], Bs[kt & 1], acc, wm, wn, gr, ctl);    \
        __syncthreads();                                               \
    }

// ---------------------------------------------------------------------------
// QKV: y = x @ W^T + b, scattered into per-head (b,h,c,t,d) layout.
// Outputs are tf32-rounded (rna) so attention MMA operands are exact.
// ---------------------------------------------------------------------------
__global__ void __launch_bounds__(256)
qkv_mma(const float* __restrict__ bq, const float* __restrict__ bk,
        const float* __restrict__ bv)
{
    __shared__ float As[2][128 * SSTR];
    __shared__ float Bs[2][128 * SSTR];

    const int tid = threadIdx.x, lane = tid & 31, warp = tid >> 5;
    const int wm = warp & 1, wn = warp >> 1;
    const int gr = lane >> 2, ctl = lane & 3;

    const int m0 = blockIdx.x * 128;
    const int mm = blockIdx.y >> 2;
    const int f0 = (blockIdx.y & 3) * 128;

    const float* gA = g_xr + (size_t)m0 * En;
    const float* gB = g_wr + (size_t)mm * En * En + (size_t)f0 * En;
    const float* bias = (mm == 0) ? bq : (mm == 1) ? bk : bv;
    float* gout = (mm == 0) ? g_q : (mm == 1) ? g_k : g_v;

    float acc[4][4][4];
    #pragma unroll
    for (int i = 0; i < 4; i++)
        #pragma unroll
        for (int j = 0; j < 4; j++)
            #pragma unroll
            for (int l = 0; l < 4; l++) acc[i][j][l] = 0.f;

    GEMM_MAINLOOP(gA, gB)

    const int fbase = f0 + wn * 32;
    #pragma unroll
    for (int mi = 0; mi < 4; mi++) {
        #pragma unroll
        for (int half = 0; half < 2; half++) {
            int r = m0 + wm * 64 + mi * 16 + gr + half * 8;
            int b = r / (Tn * Cn);
            int rem = r - b * (Tn * Cn);
            int t = rem / Cn;
            int cc = rem - t * Cn;
            #pragma unroll
            for (int ni = 0; ni < 4; ni++) {
                int f = fbase + ni * 8 + 2 * ctl;
                int h = f >> 6, d = f & 63;
                float2 o;
                o.x = tf32r(acc[mi][ni][half * 2 + 0] + bias[f]);
                o.y = tf32r(acc[mi][ni][half * 2 + 1] + bias[f + 1]);
                float* dst = gout + ((((size_t)b * Hn + h) * Cn + cc) * Tn + t) * HD + d;
                *(float2*)dst = o;
            }
        }
    }
}

// ---------------------------------------------------------------------------
// Output projection: out = g_y @ Wp^T + bp.
// ---------------------------------------------------------------------------
__global__ void __launch_bounds__(256)
proj_mma(const float* __restrict__ bp, float* __restrict__ out)
{
    __shared__ float As[2][128 * SSTR];
    __shared__ float Bs[2][128 * SSTR];

    const int tid = threadIdx.x, lane = tid & 31, warp = tid >> 5;
    const int wm = warp & 1, wn = warp >> 1;
    const int gr = lane >> 2, ctl = lane & 3;

    const int m0 = blockIdx.x * 128;
    const int f0 = blockIdx.y * 128;

    const float* gA = g_y + (size_t)m0 * En;
    const float* gB = g_wr + (size_t)3 * En * En + (size_t)f0 * En;

    float acc[4][4][4];
    #pragma unroll
    for (int i = 0; i < 4; i++)
        #pragma unroll
        for (int j = 0; j < 4; j++)
            #pragma unroll
            for (int l = 0; l < 4; l++) acc[i][j][l] = 0.f;

    GEMM_MAINLOOP(gA, gB)

    #pragma unroll
    for (int mi = 0; mi < 4; mi++) {
        #pragma unroll
        for (int half = 0; half < 2; half++) {
            int r = m0 + wm * 64 + mi * 16 + gr + half * 8;
            #pragma unroll
            for (int ni = 0; ni < 4; ni++) {
                int col = f0 + wn * 32 + ni * 8 + 2 * ctl;
                float2 o;
                o.x = acc[mi][ni][half * 2 + 0] + bp[col];
                o.y = acc[mi][ni][half * 2 + 1] + bp[col + 1];
                *(float2*)(out + (size_t)r * En + col) = o;
            }
        }
    }
}

// ---------------------------------------------------------------------------
// MMA attention, balanced causal partition.
// 1 CTA per head, 8 warps. Warp w owns two 16-row bands: rows [16w,16w+16)
// and [16(15-w), 16(15-w)+16) -> every warp does exactly 4.25 tile-units.
// Full K,V resident in smem; per-warp 16-row P buffer. Diagonal tiles skip
// fully-masked 8-col fragments (warp-uniform predicates).
// All MMA operands are exact tf32 (rna-rounded) -> no truncation bias.
// ---------------------------------------------------------------------------
#define KSTR 68   // (4g+c) lane->bank map, conflict-free K frag loads
#define VSTR 72   // (8c+g) lane->bank map, conflict-free V frag loads
#define PSTR 68
#define ATTN_SMEM_BYTES ((Tn*KSTR + Tn*VSTR + 8*16*PSTR) * 4)  // 178176

__global__ void __launch_bounds__(256, 1)
attn_kernel()
{
    extern __shared__ float smem[];
    float* Ks = smem;                       // [256][KSTR]
    float* Vs = smem + Tn * KSTR;           // [256][VSTR]

    const int hh = blockIdx.x;
    const int c  = hh % Cn;
    const int bh = hh / Cn;
    const int h  = bh % Hn;
    const int b  = bh / Hn;

    const float* qp = g_q + (size_t)hh * Tn * HD;
    const float* kp = g_k + (size_t)hh * Tn * HD;
    const float* vp = g_v + (size_t)hh * Tn * HD;

    const int tid  = threadIdx.x;
    const int lane = tid & 31, warp = tid >> 5;
    const int gr   = lane >> 2, ctl = lane & 3;

    float* Pw = smem + Tn * KSTR + Tn * VSTR + warp * 16 * PSTR;  // [16][PSTR]

    // ---- load full K and V into smem ----
    #pragma unroll
    for (int it = 0; it < 16; it++) {
        int idx = it * 256 + tid;           // float4 index over 256x64
        int row = idx >> 4;
        int c4  = (idx & 15) * 4;
        cpasync16(Ks + row * KSTR + c4, kp + row * HD + c4);
        cpasync16(Vs + row * VSTR + c4, vp + row * HD + c4);
    }
    asm volatile("cp.async.commit_group;\n" ::);
    asm volatile("cp.async.wait_group 0;\n" ::);
    __syncthreads();

    #pragma unroll 1
    for (int band = 0; band < 2; band++) {
        const int rb = (band == 0) ? warp * 16 : (15 - warp) * 16;

        // ---- stage this band's Q (scaled) into Pw, build A-fragments ----
        __syncwarp();
        #pragma unroll
        for (int it = 0; it < 8; it++) {
            int idx = it * 32 + lane;       // float4 index over 16x16
            int row = idx >> 4;
            int c4  = (idx & 15) * 4;
            float4 v4 = *(const float4*)(qp + (size_t)(rb + row) * HD + c4);
            v4.x *= 0.125f; v4.y *= 0.125f; v4.z *= 0.125f; v4.w *= 0.125f;
            *(float4*)(Pw + row * PSTR + c4) = v4;
        }
        __syncwarp();

        uint32_t aq[8][4];
        #pragma unroll
        for (int ks = 0; ks < 8; ks++) {
            const float* p = Pw + gr * PSTR + ks * 8 + ctl;
            aq[ks][0] = __float_as_uint(p[0]);
            aq[ks][1] = __float_as_uint(p[8 * PSTR]);
            aq[ks][2] = __float_as_uint(p[4]);
            aq[ks][3] = __float_as_uint(p[8 * PSTR + 4]);
        }

        float oacc[8][4];
        #pragma unroll
        for (int nt = 0; nt < 8; nt++)
            #pragma unroll
            for (int e = 0; e < 4; e++) oacc[nt][e] = 0.f;
        float lsum[2] = {0.f, 0.f};

        const int ntiles = rb / 64 + 1;

        #pragma unroll
        for (int jt = 0; jt < 4; jt++) {
            if (jt >= ntiles) break;
            const int j0 = jt * 64;
            int nfr = (rb + 15 - j0) / 8 + 1;
            if (nfr > 8) nfr = 8;

            __syncwarp();   // previous PV reads of Pw done before overwrite

            // ---- S = Q @ K_tile^T ----
            float s[8][4];
            #pragma unroll
            for (int nt = 0; nt < 8; nt++)
                #pragma unroll
                for (int e = 0; e < 4; e++) s[nt][e] = 0.f;

            #pragma unroll
            for (int ks = 0; ks < 8; ks++) {
                uint32_t bfr[8][2];
                #pragma unroll
                for (int nt = 0; nt < 8; nt++) {
                    if (nt < nfr) {
                        const float* p = Ks + (j0 + nt * 8 + gr) * KSTR + ks * 8 + ctl;
                        bfr[nt][0] = __float_as_uint(p[0]);
                        bfr[nt][1] = __float_as_uint(p[4]);
                    }
                }
                #pragma unroll
                for (int nt = 0; nt < 8; nt++)
                    if (nt < nfr)
                        mma_tf32(s[nt], aq[ks], bfr[nt]);
            }

            // ---- mask + exp + rna-round + store P + lsum ----
            const int row0 = rb + gr, row1 = rb + gr + 8;
            #pragma unroll
            for (int nt = 0; nt < 8; nt++) {
                if (nt < nfr) {
                    const int col = j0 + nt * 8 + 2 * ctl;
                    float p00 = (col     <= row0) ? tf32r(__expf(s[nt][0])) : 0.f;
                    float p01 = (col + 1 <= row0) ? tf32r(__expf(s[nt][1])) : 0.f;
                    float p10 = (col     <= row1) ? tf32r(__expf(s[nt][2])) : 0.f;
                    float p11 = (col + 1 <= row1) ? tf32r(__expf(s[nt][3])) : 0.f;
                    lsum[0] += p00 + p01;
                    lsum[1] += p10 + p11;
                    float2 v0 = {p00, p01}, v1 = {p10, p11};
                    *(float2*)(Pw + gr * PSTR + nt * 8 + 2 * ctl)       = v0;
                    *(float2*)(Pw + (gr + 8) * PSTR + nt * 8 + 2 * ctl) = v1;
                }
            }
            __syncwarp();

            // ---- O += P @ V_tile ----
            #pragma unroll
            for (int ks = 0; ks < 8; ks++) {
                if (ks < nfr) {
                    uint32_t ap[4];
                    const float* p = Pw + gr * PSTR + ks * 8 + ctl;
                    ap[0] = __float_as_uint(p[0]);
                    ap[1] = __float_as_uint(p[8 * PSTR]);
                    ap[2] = __float_as_uint(p[4]);
                    ap[3] = __float_as_uint(p[8 * PSTR + 4]);
                    #pragma unroll
                    for (int nt = 0; nt < 8; nt++) {
                        uint32_t bv2[2];
                        const float* pv = Vs + (j0 + ks * 8 + ctl) * VSTR + nt * 8 + gr;
                        bv2[0] = __float_as_uint(pv[0]);
                        bv2[1] = __float_as_uint(pv[4 * VSTR]);
                        mma_tf32(oacc[nt], ap, bv2);
                    }
                }
            }
        }

        // ---- finalize band: reduce lsum over ctl group, normalize, write ----
        float inv[2];
        #pragma unroll
        for (int hf = 0; hf < 2; hf++) {
            float l = lsum[hf];
            l += __shfl_xor_sync(0xffffffff, l, 1);
            l += __shfl_xor_sync(0xffffffff, l, 2);
            inv[hf] = 1.f / l;
        }

        #pragma unroll
        for (int hf = 0; hf < 2; hf++) {
            int trow = rb + gr + 8 * hf;
            float* yp = g_y + (size_t)(b * Tn + trow) * (Hn * Cn * HD) + (h * Cn + c) * HD;
            #pragma unroll
            for (int nt = 0; nt < 8; nt++) {
                float2 o;
                o.x = tf32r(oacc[nt][hf * 2 + 0] * inv[hf]);
                o.y = tf32r(oacc[nt][hf * 2 + 1] * inv[hf]);
                *(float2*)(yp + nt * 8 + 2 * ctl) = o;
            }
        }
    }
}

// ---------------------------------------------------------------------------
extern "C" void kernel_launch(void* const* d_in, const int* in_sizes, int n_in,
                              void* d_out, int out_size)
{
    const float* x  = (const float*)d_in[0];
    const float* Wq = (const float*)d_in[1];
    const float* bq = (const float*)d_in[2];
    const float* Wk = (const float*)d_in[3];
    const float* bk = (const float*)d_in[4];
    const float* Wv = (const float*)d_in[5];
    const float* bv = (const float*)d_in[6];
    const float* Wp = (const float*)d_in[7];
    const float* bp = (const float*)d_in[8];
    float* out = (float*)d_out;

    cudaFuncSetAttribute(attn_kernel, cudaFuncAttributeMaxDynamicSharedMemorySize,
                         ATTN_SMEM_BYTES);

    round_x_kernel<<<(NTOK * En / 4) / 256, 256>>>(x);
    round_w_kernel<<<(4 * En * En / 4) / 256, 256>>>(Wq, Wk, Wv, Wp);
    qkv_mma<<<dim3(NTOK / 128, 12), 256>>>(bq, bk, bv);
    attn_kernel<<<NHEADS, 256, ATTN_SMEM_BYTES>>>();
    proj_mma<<<dim3(NTOK / 128, 4), 256>>>(bp, out);
}